// round 9
// baseline (speedup 1.0000x reference)
#include <cuda_runtime.h>
#include <cstdint>

// ---------------------------------------------------------------------------
// GIN: 3 layers of { rst = h + segment_sum(h[src], dst); h = MLP2(rst) }
// N=100000, E=1600000, D=128.
//   - CSR build per launch (int atomics only)
//   - FUSED layer kernel: gather-aggregate directly into smem tile (edge loop
//     unrolled x8 for MLP ~8 -> L2-BW bound, not latency bound), then
//     2-GEMM MLP with packed fp32 FFMA2 (fma.rn.f32x2).
//     TILE_M=64, 256 threads, ~98KB smem -> 2 blocks/SM.
//   - Last layer has no relu anywhere -> collapse its two GEMMs into one
//     via precomputed W12 = W1@W2, b12 = b1@W2 + b2.
// ---------------------------------------------------------------------------

#define DIM 128
#define MAXN 100000
#define MAXE 1600000
#define TILE_M 64
#define SA_PITCH 132
#define SMEM_FLOATS (128 * 128 + TILE_M * SA_PITCH + 256)
#define SMEM_BYTES (SMEM_FLOATS * 4)
#define SCAN_CHUNK 2048
#define MAX_SCAN_BLOCKS 64

// scratch (device globals: no allocation allowed)
__device__ int   g_deg[MAXN];
__device__ int   g_rowptr[MAXN + 1];
__device__ int   g_cursor[MAXN];
__device__ int   g_col[MAXE];
__device__ int   g_bsum[MAX_SCAN_BLOCKS];
__device__ __align__(16) float g_hA [(size_t)MAXN * DIM];
__device__ __align__(16) float g_hB [(size_t)MAXN * DIM];
__device__ __align__(16) float g_W12[DIM * DIM];
__device__ __align__(16) float g_b12[DIM];

// ------------------------- f32x2 helpers ------------------------------------

__device__ __forceinline__ unsigned long long pack2(float x, float y) {
    unsigned long long r;
    asm("mov.b64 %0, {%1, %2};" : "=l"(r) : "f"(x), "f"(y));
    return r;
}
__device__ __forceinline__ void unpack2(unsigned long long v, float& x, float& y) {
    asm("mov.b64 {%0, %1}, %2;" : "=f"(x), "=f"(y) : "l"(v));
}
__device__ __forceinline__ void fma2(unsigned long long& d,
                                     unsigned long long a, unsigned long long b) {
    asm("fma.rn.f32x2 %0, %1, %2, %0;" : "+l"(d) : "l"(a), "l"(b));
}

// -------------------------- CSR build ---------------------------------------

__global__ void k_zero_deg(int n) {
    int i = blockIdx.x * blockDim.x + threadIdx.x;
    if (i < n) g_deg[i] = 0;
}

__global__ void k_hist(const int* __restrict__ dst, int e) {
    int i = blockIdx.x * blockDim.x + threadIdx.x;
    if (i < e) atomicAdd(&g_deg[dst[i]], 1);
}

__global__ void k_scan_reduce(int n) {
    __shared__ int s[256];
    int tid = threadIdx.x;
    int base = blockIdx.x * SCAN_CHUNK + tid * 8;
    int tot = 0;
#pragma unroll
    for (int j = 0; j < 8; ++j) {
        int idx = base + j;
        tot += (idx < n) ? g_deg[idx] : 0;
    }
    s[tid] = tot;
    __syncthreads();
    for (int off = 128; off > 0; off >>= 1) {
        if (tid < off) s[tid] += s[tid + off];
        __syncthreads();
    }
    if (tid == 0) g_bsum[blockIdx.x] = s[0];
}

__global__ void k_scan_bsum(int nb, int e, int n) {
    __shared__ int s[64];
    int t = threadIdx.x;
    int v = (t < nb) ? g_bsum[t] : 0;
    s[t] = v;
    __syncthreads();
    for (int off = 1; off < 64; off <<= 1) {
        int a = (t >= off) ? s[t - off] : 0;
        __syncthreads();
        s[t] += a;
        __syncthreads();
    }
    if (t < nb) g_bsum[t] = s[t] - v;
    if (t == 0) g_rowptr[n] = e;
}

__global__ void k_scan_final(int n) {
    __shared__ int s[256];
    int tid = threadIdx.x;
    int base = blockIdx.x * SCAN_CHUNK + tid * 8;
    int v[8];
    int run = 0;
#pragma unroll
    for (int j = 0; j < 8; ++j) {
        int idx = base + j;
        int t = (idx < n) ? g_deg[idx] : 0;
        v[j] = run;
        run += t;
    }
    int tot = run;
    s[tid] = tot;
    __syncthreads();
    for (int off = 1; off < 256; off <<= 1) {
        int add = (tid >= off) ? s[tid - off] : 0;
        __syncthreads();
        s[tid] += add;
        __syncthreads();
    }
    int texcl = s[tid] - tot;
    int pref = g_bsum[blockIdx.x] + texcl;
#pragma unroll
    for (int j = 0; j < 8; ++j) {
        int idx = base + j;
        if (idx < n) {
            int r = pref + v[j];
            g_rowptr[idx] = r;
            g_cursor[idx] = r;
        }
    }
}

__global__ void k_fill(const int* __restrict__ src, const int* __restrict__ dst, int e) {
    int i = blockIdx.x * blockDim.x + threadIdx.x;
    if (i < e) {
        int d = dst[i];
        int pos = atomicAdd(&g_cursor[d], 1);
        g_col[pos] = src[i];
    }
}

// -------------------- last-layer weight folding ------------------------------
// W12[k][n] = sum_j W1[k][j] * W2[j][n];  b12[n] = sum_j b1[j]*W2[j][n] + b2[n]

__global__ void k_wfuse(const float* __restrict__ W1g, const float* __restrict__ W2g) {
    __shared__ float row[128];
    int k = blockIdx.x, nn = threadIdx.x;
    row[nn] = W1g[k * 128 + nn];
    __syncthreads();
    float acc = 0.f;
#pragma unroll 8
    for (int j = 0; j < 128; ++j) acc += row[j] * W2g[j * 128 + nn];
    g_W12[k * 128 + nn] = acc;
}

__global__ void k_bfuse(const float* __restrict__ b1g, const float* __restrict__ W2g,
                        const float* __restrict__ b2g) {
    __shared__ float bb[128];
    int nn = threadIdx.x;
    bb[nn] = b1g[nn];
    __syncthreads();
    float acc = b2g[nn];
#pragma unroll 8
    for (int j = 0; j < 128; ++j) acc += bb[j] * W2g[j * 128 + nn];
    g_b12[nn] = acc;
}

// ---------------------- shared device pieces ---------------------------------

// gather prologue: 8 warps x 8 rows; lane owns one float4 of the row.
// Edge loop batched x8 / x4 so up to 8 LDG.128 are in flight per warp
// (addresses independent of the running sum) -> latency hidden, L2-BW bound.
__device__ __forceinline__ void gather_tile(const float* __restrict__ hin,
                                            float* __restrict__ sA,
                                            int row0, int n, int tid) {
    const int wid = tid >> 5, lane = tid & 31;
    const float4* __restrict__ h4 = (const float4*)hin;
#pragma unroll 1
    for (int rr = 0; rr < 8; ++rr) {
        int r  = wid * 8 + rr;
        int rg = row0 + r;
        float4 a = make_float4(0.f, 0.f, 0.f, 0.f);
        if (rg < n) {
            a = h4[(size_t)rg * 32 + lane];       // self, (1+eps)=1
            int i = g_rowptr[rg];
            const int epos = g_rowptr[rg + 1];
            for (; i + 8 <= epos; i += 8) {
                int s0 = g_col[i],     s1 = g_col[i + 1];
                int s2 = g_col[i + 2], s3 = g_col[i + 3];
                int s4 = g_col[i + 4], s5 = g_col[i + 5];
                int s6 = g_col[i + 6], s7 = g_col[i + 7];
                float4 v0 = __ldg(&h4[(size_t)s0 * 32 + lane]);
                float4 v1 = __ldg(&h4[(size_t)s1 * 32 + lane]);
                float4 v2 = __ldg(&h4[(size_t)s2 * 32 + lane]);
                float4 v3 = __ldg(&h4[(size_t)s3 * 32 + lane]);
                float4 v4 = __ldg(&h4[(size_t)s4 * 32 + lane]);
                float4 v5 = __ldg(&h4[(size_t)s5 * 32 + lane]);
                float4 v6 = __ldg(&h4[(size_t)s6 * 32 + lane]);
                float4 v7 = __ldg(&h4[(size_t)s7 * 32 + lane]);
                float4 p0, p1, p2, p3, q0, q1;
                p0.x = v0.x + v1.x; p0.y = v0.y + v1.y; p0.z = v0.z + v1.z; p0.w = v0.w + v1.w;
                p1.x = v2.x + v3.x; p1.y = v2.y + v3.y; p1.z = v2.z + v3.z; p1.w = v2.w + v3.w;
                p2.x = v4.x + v5.x; p2.y = v4.y + v5.y; p2.z = v4.z + v5.z; p2.w = v4.w + v5.w;
                p3.x = v6.x + v7.x; p3.y = v6.y + v7.y; p3.z = v6.z + v7.z; p3.w = v6.w + v7.w;
                q0.x = p0.x + p1.x; q0.y = p0.y + p1.y; q0.z = p0.z + p1.z; q0.w = p0.w + p1.w;
                q1.x = p2.x + p3.x; q1.y = p2.y + p3.y; q1.z = p2.z + p3.z; q1.w = p2.w + p3.w;
                a.x += q0.x + q1.x; a.y += q0.y + q1.y;
                a.z += q0.z + q1.z; a.w += q0.w + q1.w;
            }
            if (i + 4 <= epos) {
                int s0 = g_col[i],     s1 = g_col[i + 1];
                int s2 = g_col[i + 2], s3 = g_col[i + 3];
                float4 v0 = __ldg(&h4[(size_t)s0 * 32 + lane]);
                float4 v1 = __ldg(&h4[(size_t)s1 * 32 + lane]);
                float4 v2 = __ldg(&h4[(size_t)s2 * 32 + lane]);
                float4 v3 = __ldg(&h4[(size_t)s3 * 32 + lane]);
                float4 p0, p1;
                p0.x = v0.x + v1.x; p0.y = v0.y + v1.y; p0.z = v0.z + v1.z; p0.w = v0.w + v1.w;
                p1.x = v2.x + v3.x; p1.y = v2.y + v3.y; p1.z = v2.z + v3.z; p1.w = v2.w + v3.w;
                a.x += p0.x + p1.x; a.y += p0.y + p1.y;
                a.z += p0.z + p1.z; a.w += p0.w + p1.w;
                i += 4;
            }
            for (; i < epos; ++i) {
                int sn = g_col[i];
                float4 v = __ldg(&h4[(size_t)sn * 32 + lane]);
                a.x += v.x; a.y += v.y; a.z += v.z; a.w += v.w;
            }
        }
        *(float4*)&sA[r * SA_PITCH + lane * 4] = a;
    }
}

// one 64x128x128 GEMM phase with f32x2 accumulators.
// trow = tid>>5 (rows trow*8..+7), tcol = tid&31 (cols tcol*4..+3)
__device__ __forceinline__ void gemm_phase(const float* __restrict__ sA,
                                           const float* __restrict__ sW,
                                           const float* __restrict__ bias,
                                           int r0, int c0,
                                           unsigned long long acc[8][2]) {
    unsigned long long bb0 = pack2(bias[c0],     bias[c0 + 1]);
    unsigned long long bb1 = pack2(bias[c0 + 2], bias[c0 + 3]);
#pragma unroll
    for (int i = 0; i < 8; ++i) { acc[i][0] = bb0; acc[i][1] = bb1; }
#pragma unroll 1
    for (int k0 = 0; k0 < 128; k0 += 4) {
        float4 a4[8];
#pragma unroll
        for (int i = 0; i < 8; ++i)
            a4[i] = *(const float4*)&sA[(r0 + i) * SA_PITCH + k0];
#pragma unroll
        for (int kk = 0; kk < 4; ++kk) {
            ulonglong2 w = *(const ulonglong2*)&sW[(k0 + kk) * 128 + c0];
#pragma unroll
            for (int i = 0; i < 8; ++i) {
                float av = ((const float*)&a4[i])[kk];
                unsigned long long aa = pack2(av, av);
                fma2(acc[i][0], aa, w.x);
                fma2(acc[i][1], aa, w.y);
            }
        }
    }
}

// ---------------------- fused layer: agg + 2-GEMM MLP (relu) -----------------

__global__ void __launch_bounds__(256, 2)
k_gin(const float* __restrict__ hin,
      const float* __restrict__ W1g, const float* __restrict__ b1g,
      const float* __restrict__ W2g, const float* __restrict__ b2g,
      float* __restrict__ out, int n) {
    extern __shared__ float smem[];
    float* sW    = smem;                   // 128*128
    float* sA    = sW + 128 * 128;         // 64*SA_PITCH
    float* sBias = sA + TILE_M * SA_PITCH; // 256

    const int tid  = threadIdx.x;
    const int row0 = blockIdx.x * TILE_M;

    if (tid < 128)      sBias[tid] = b1g[tid];
    else                sBias[tid] = b2g[tid - 128];

    // W1 -> sW (4096 float4 by 256 threads)
    {
        const float4* w4 = (const float4*)W1g;
        float4* s4 = (float4*)sW;
#pragma unroll
        for (int it = 0; it < 16; ++it) s4[tid + it * 256] = w4[tid + it * 256];
    }
    // aggregate tile directly into sA
    gather_tile(hin, sA, row0, n, tid);
    __syncthreads();

    const int trow = tid >> 5;   // 0..7
    const int tcol = tid & 31;   // 0..31
    const int r0 = trow * 8, c0 = tcol * 4;

    unsigned long long acc[8][2];

    // ---- phase 1: h1 = relu(A @ W1 + b1) ----
    gemm_phase(sA, sW, sBias, r0, c0, acc);
    __syncthreads();   // all phase-1 reads complete

    // h1 -> sA (overwrite), W2 -> sW
#pragma unroll
    for (int i = 0; i < 8; ++i) {
#pragma unroll
        for (int p = 0; p < 2; ++p) {
            float x, y;
            unpack2(acc[i][p], x, y);
            x = fmaxf(x, 0.f); y = fmaxf(y, 0.f);
            *(unsigned long long*)&sA[(r0 + i) * SA_PITCH + c0 + 2 * p] = pack2(x, y);
        }
    }
    {
        const float4* w4 = (const float4*)W2g;
        float4* s4 = (float4*)sW;
#pragma unroll
        for (int it = 0; it < 16; ++it) s4[tid + it * 256] = w4[tid + it * 256];
    }
    __syncthreads();

    // ---- phase 2: out = relu(h1 @ W2 + b2) ----
    gemm_phase(sA, sW, sBias + 128, r0, c0, acc);

#pragma unroll
    for (int i = 0; i < 8; ++i) {
        int rg = row0 + r0 + i;
        if (rg < n) {
            float x0, y0, x1, y1;
            unpack2(acc[i][0], x0, y0);
            unpack2(acc[i][1], x1, y1);
            x0 = fmaxf(x0, 0.f); y0 = fmaxf(y0, 0.f);
            x1 = fmaxf(x1, 0.f); y1 = fmaxf(y1, 0.f);
            ((float4*)out)[(size_t)rg * 32 + tcol] = make_float4(x0, y0, x1, y1);
        }
    }
}

// ---------------- fused last layer: agg + single folded GEMM -----------------

__global__ void __launch_bounds__(256, 2)
k_gin_last(const float* __restrict__ hin, float* __restrict__ out, int n) {
    extern __shared__ float smem[];
    float* sW    = smem;
    float* sA    = sW + 128 * 128;
    float* sBias = sA + TILE_M * SA_PITCH;

    const int tid  = threadIdx.x;
    const int row0 = blockIdx.x * TILE_M;

    if (tid < 128) sBias[tid] = g_b12[tid];

    {
        const float4* w4 = (const float4*)g_W12;
        float4* s4 = (float4*)sW;
#pragma unroll
        for (int it = 0; it < 16; ++it) s4[tid + it * 256] = w4[tid + it * 256];
    }
    gather_tile(hin, sA, row0, n, tid);
    __syncthreads();

    const int trow = tid >> 5;
    const int tcol = tid & 31;
    const int r0 = trow * 8, c0 = tcol * 4;

    unsigned long long acc[8][2];
    gemm_phase(sA, sW, sBias, r0, c0, acc);

#pragma unroll
    for (int i = 0; i < 8; ++i) {
        int rg = row0 + r0 + i;
        if (rg < n) {
            float x0, y0, x1, y1;
            unpack2(acc[i][0], x0, y0);
            unpack2(acc[i][1], x1, y1);
            ((float4*)out)[(size_t)rg * 32 + tcol] = make_float4(x0, y0, x1, y1);
        }
    }
}

// ---------------------------- host ------------------------------------------

extern "C" void kernel_launch(void* const* d_in, const int* in_sizes, int n_in,
                              void* d_out, int out_size) {
    const float* feat = (const float*)d_in[0];
    const float* W1   = (const float*)d_in[1];
    const float* b1   = (const float*)d_in[2];
    const float* W2   = (const float*)d_in[3];
    const float* b2   = (const float*)d_in[4];
    const int*   src  = (const int*)d_in[5];
    const int*   dst  = (const int*)d_in[6];

    const int n = in_sizes[0] / DIM;
    const int e = in_sizes[5];

    cudaFuncSetAttribute((const void*)k_gin,
                         cudaFuncAttributeMaxDynamicSharedMemorySize, SMEM_BYTES);
    cudaFuncSetAttribute((const void*)k_gin_last,
                         cudaFuncAttributeMaxDynamicSharedMemorySize, SMEM_BYTES);

    float *hA, *hB;
    cudaGetSymbolAddress((void**)&hA, g_hA);
    cudaGetSymbolAddress((void**)&hB, g_hB);

    // ---- CSR build + last-layer weight folding ----
    k_zero_deg<<<(n + 255) / 256, 256>>>(n);
    k_hist<<<(e + 255) / 256, 256>>>(dst, e);
    const int nb = (n + SCAN_CHUNK - 1) / SCAN_CHUNK;
    k_scan_reduce<<<nb, 256>>>(n);
    k_scan_bsum<<<1, 64>>>(nb, e, n);
    k_scan_final<<<nb, 256>>>(n);
    k_fill<<<(e + 255) / 256, 256>>>(src, dst, e);
    k_wfuse<<<128, 128>>>(W1 + 2 * DIM * DIM, W2 + 2 * DIM * DIM);
    k_bfuse<<<1, 128>>>(b1 + 2 * DIM, W2 + 2 * DIM * DIM, b2 + 2 * DIM);

    const int blocks = (n + TILE_M - 1) / TILE_M;

    // ---- layer 0 ----
    k_gin<<<blocks, 256, SMEM_BYTES>>>(
        feat, W1 + 0 * DIM * DIM, b1 + 0 * DIM, W2 + 0 * DIM * DIM, b2 + 0 * DIM, hA, n);
    // ---- layer 1 ----
    k_gin<<<blocks, 256, SMEM_BYTES>>>(
        hA, W1 + 1 * DIM * DIM, b1 + 1 * DIM, W2 + 1 * DIM * DIM, b2 + 1 * DIM, hB, n);
    // ---- layer 2 (folded single GEMM, no relu) ----
    k_gin_last<<<blocks, 256, SMEM_BYTES>>>(hB, (float*)d_out, n);
}